// round 3
// baseline (speedup 1.0000x reference)
#include <cuda_runtime.h>
#include <math.h>

#define N1_TOT 65536   // 4 * 16384 fine points
#define N2_TOT 16384   // 4 * 4096 coarse points
#define NPS1   16384
#define NPS2   4096
#define CIN    512
#define COUT   256

// scratch for h2 (branch-2 features), 16 MB
__device__ float g_h2[N2_TOT * COUT];

// ---------------------------------------------------------------------------
// GEMM + bias + eval-BN + ReLU.
// C[n, m] = relu( alpha[m] * (sum_k A[n,k] * W[m,k]) + beta[m] )
// alpha[m] = gam[m]/sqrt(var[m]+eps), beta[m] = (bias[m]-mu[m])*alpha[m]+bet[m]
// Tile 128x128, BK=16, 256 threads, 8x8 per thread.
// ---------------------------------------------------------------------------
__global__ void __launch_bounds__(256, 2)
gemm_bn_relu(const float* __restrict__ A, const float* __restrict__ W,
             const float* __restrict__ bias, const float* __restrict__ gam,
             const float* __restrict__ bet, const float* __restrict__ mu,
             const float* __restrict__ var, float* __restrict__ C, int Kd)
{
    __shared__ float As[16][128];
    __shared__ float Bs[16][128];

    const int tid = threadIdx.x;
    const int tx = tid & 15;      // 0..15 -> output cols
    const int ty = tid >> 4;      // 0..15 -> output rows

    const float* Ab = A + (size_t)blockIdx.x * 128 * Kd;
    const float* Wb = W + (size_t)blockIdx.y * 128 * Kd;

    float acc[8][8];
#pragma unroll
    for (int i = 0; i < 8; i++)
#pragma unroll
        for (int j = 0; j < 8; j++) acc[i][j] = 0.0f;

    for (int kt = 0; kt < Kd; kt += 16) {
#pragma unroll
        for (int i = 0; i < 2; i++) {
            int idx = tid + i * 256;           // 0..511
            int row = idx >> 2;                // 0..127
            int c4  = idx & 3;                 // 0..3 (float4 within 16 k's)
            float4 va = *(const float4*)(Ab + (size_t)row * Kd + kt + c4 * 4);
            As[c4 * 4 + 0][row] = va.x;
            As[c4 * 4 + 1][row] = va.y;
            As[c4 * 4 + 2][row] = va.z;
            As[c4 * 4 + 3][row] = va.w;
            float4 vb = *(const float4*)(Wb + (size_t)row * Kd + kt + c4 * 4);
            Bs[c4 * 4 + 0][row] = vb.x;
            Bs[c4 * 4 + 1][row] = vb.y;
            Bs[c4 * 4 + 2][row] = vb.z;
            Bs[c4 * 4 + 3][row] = vb.w;
        }
        __syncthreads();

#pragma unroll
        for (int k = 0; k < 16; k++) {
            float a[8], b[8];
            *(float4*)(a)     = *(const float4*)&As[k][ty * 4];
            *(float4*)(a + 4) = *(const float4*)&As[k][64 + ty * 4];
            *(float4*)(b)     = *(const float4*)&Bs[k][tx * 4];
            *(float4*)(b + 4) = *(const float4*)&Bs[k][64 + tx * 4];
#pragma unroll
            for (int i = 0; i < 8; i++)
#pragma unroll
                for (int j = 0; j < 8; j++)
                    acc[i][j] = fmaf(a[i], b[j], acc[i][j]);
        }
        __syncthreads();
    }

    // epilogue: per-column BN affine + relu
    float al[8], be_[8];
#pragma unroll
    for (int jh = 0; jh < 2; jh++) {
#pragma unroll
        for (int j = 0; j < 4; j++) {
            int c = blockIdx.y * 128 + jh * 64 + tx * 4 + j;
            float s = gam[c] * rsqrtf(var[c] + 1e-5f);
            al[jh * 4 + j] = s;
            be_[jh * 4 + j] = (bias[c] - mu[c]) * s + bet[c];
        }
    }

#pragma unroll
    for (int ih = 0; ih < 2; ih++) {
#pragma unroll
        for (int i = 0; i < 4; i++) {
            size_t row = (size_t)blockIdx.x * 128 + ih * 64 + ty * 4 + i;
#pragma unroll
            for (int jh = 0; jh < 2; jh++) {
                float4 o;
                o.x = fmaxf(fmaf(acc[ih * 4 + i][jh * 4 + 0], al[jh * 4 + 0], be_[jh * 4 + 0]), 0.f);
                o.y = fmaxf(fmaf(acc[ih * 4 + i][jh * 4 + 1], al[jh * 4 + 1], be_[jh * 4 + 1]), 0.f);
                o.z = fmaxf(fmaf(acc[ih * 4 + i][jh * 4 + 2], al[jh * 4 + 2], be_[jh * 4 + 2]), 0.f);
                o.w = fmaxf(fmaf(acc[ih * 4 + i][jh * 4 + 3], al[jh * 4 + 3], be_[jh * 4 + 3]), 0.f);
                int col = blockIdx.y * 128 + jh * 64 + tx * 4;
                *(float4*)(C + row * COUT + col) = o;
            }
        }
    }
}

// ---------------------------------------------------------------------------
// kNN (k=3) inverse-distance interpolation + accumulate into out (which
// already holds h1). One block = 256 consecutive queries (same scene since
// 16384 % 256 == 0). Phase 1: exact top-3 scan of the scene's 4096 support
// points through smem tiles. Phase 2: block-cooperative coalesced gather of
// h2 rows, weighted sum, add to out.
// ---------------------------------------------------------------------------
#define PTILE 512

__global__ void __launch_bounds__(256)
interp_kernel(const float* __restrict__ p1, const float* __restrict__ p2,
              const float* __restrict__ h2, float* __restrict__ out)
{
    __shared__ float sp[PTILE * 3];
    __shared__ float sq[256 * 3];
    __shared__ float sw[3][256];
    __shared__ int   si[3][256];

    const int tid = threadIdx.x;
    const int q0 = blockIdx.x * 256;
    const int scene = q0 / NPS1;

    // cooperative coalesced load of this block's query coords
    for (int j = tid; j < 256 * 3; j += 256) sq[j] = p1[(size_t)q0 * 3 + j];
    __syncthreads();
    const float qx = sq[tid * 3 + 0];
    const float qy = sq[tid * 3 + 1];
    const float qz = sq[tid * 3 + 2];

    float b0 = 3.4e38f, b1 = 3.4e38f, b2 = 3.4e38f;
    int   i0 = 0, i1 = 0, i2 = 0;

    const float* pb = p2 + (size_t)scene * NPS2 * 3;

    for (int t0 = 0; t0 < NPS2; t0 += PTILE) {
        __syncthreads();
        for (int j = tid; j < PTILE * 3; j += 256) sp[j] = pb[(size_t)t0 * 3 + j];
        __syncthreads();

#pragma unroll 8
        for (int j = 0; j < PTILE; j++) {
            float dx = qx - sp[j * 3 + 0];
            float dy = qy - sp[j * 3 + 1];
            float dz = qz - sp[j * 3 + 2];
            float d = fmaf(dx, dx, fmaf(dy, dy, dz * dz));
            if (d < b2) {
                int idx = t0 + j;
                if (d < b1) {
                    b2 = b1; i2 = i1;
                    if (d < b0) { b1 = b0; i1 = i0; b0 = d; i0 = idx; }
                    else        { b1 = d;  i1 = idx; }
                } else { b2 = d; i2 = idx; }
            }
        }
    }

    // inverse-distance weights (matches reference formula exactly)
    float w0 = 1.0f / (sqrtf(fmaxf(b0, 1e-12f)) + 1e-8f);
    float w1 = 1.0f / (sqrtf(fmaxf(b1, 1e-12f)) + 1e-8f);
    float w2 = 1.0f / (sqrtf(fmaxf(b2, 1e-12f)) + 1e-8f);
    float ws = w0 + w1 + w2;
    w0 /= ws; w1 /= ws; w2 /= ws;

    sw[0][tid] = w0; sw[1][tid] = w1; sw[2][tid] = w2;
    si[0][tid] = i0; si[1][tid] = i1; si[2][tid] = i2;
    __syncthreads();

    // phase 2: coalesced weighted gather, one query at a time; tid = channel
    const float* h2b = h2 + (size_t)scene * NPS2 * COUT;
#pragma unroll 2
    for (int qq = 0; qq < 256; qq++) {
        float a0 = sw[0][qq], a1 = sw[1][qq], a2 = sw[2][qq];
        const float* f0 = h2b + (size_t)si[0][qq] * COUT;
        const float* f1 = h2b + (size_t)si[1][qq] * COUT;
        const float* f2 = h2b + (size_t)si[2][qq] * COUT;
        size_t o = (size_t)(q0 + qq) * COUT + tid;
        float v = out[o];
        v = fmaf(a0, f0[tid], v);
        v = fmaf(a1, f1[tid], v);
        v = fmaf(a2, f2[tid], v);
        out[o] = v;
    }
}

// ---------------------------------------------------------------------------
extern "C" void kernel_launch(void* const* d_in, const int* in_sizes, int n_in,
                              void* d_out, int out_size)
{
    const float* p1  = (const float*)d_in[0];
    const float* x1  = (const float*)d_in[1];
    const float* p2  = (const float*)d_in[2];
    const float* x2  = (const float*)d_in[3];
    const float* W1  = (const float*)d_in[4];
    const float* b1p = (const float*)d_in[5];
    const float* g1p = (const float*)d_in[6];
    const float* be1 = (const float*)d_in[7];
    const float* m1p = (const float*)d_in[8];
    const float* v1p = (const float*)d_in[9];
    const float* W2  = (const float*)d_in[10];
    const float* b2p = (const float*)d_in[11];
    const float* g2p = (const float*)d_in[12];
    const float* be2 = (const float*)d_in[13];
    const float* m2p = (const float*)d_in[14];
    const float* v2p = (const float*)d_in[15];
    float* out = (float*)d_out;

    float* h2ptr = nullptr;
    cudaGetSymbolAddress((void**)&h2ptr, g_h2);

    // branch 1: h1 -> out
    dim3 grid1(N1_TOT / 128, COUT / 128);
    gemm_bn_relu<<<grid1, 256>>>(x1, W1, b1p, g1p, be1, m1p, v1p, out, COUT);

    // branch 2: h2 -> scratch
    dim3 grid2(N2_TOT / 128, COUT / 128);
    gemm_bn_relu<<<grid2, 256>>>(x2, W2, b2p, g2p, be2, m2p, v2p, h2ptr, CIN);

    // kNN interpolation + add
    interp_kernel<<<N1_TOT / 256, 256>>>(p1, p2, h2ptr, out);
}

// round 4
// speedup vs baseline: 1.0597x; 1.0597x over previous
#include <cuda_runtime.h>
#include <math.h>

#define N1_TOT 65536   // 4 * 16384 fine points
#define N2_TOT 16384   // 4 * 4096 coarse points
#define NPS1   16384
#define NPS2   4096
#define CIN    512
#define COUT   256

typedef unsigned long long u64;

// scratch for h2 (branch-2 features), 16 MB
__device__ float g_h2[N2_TOT * COUT];

__device__ __forceinline__ u64 fma2(u64 a, u64 b, u64 c) {
    u64 d;
    asm("fma.rn.f32x2 %0, %1, %2, %3;" : "=l"(d) : "l"(a), "l"(b), "l"(c));
    return d;
}
__device__ __forceinline__ u64 pack2(float x) {
    u64 d;
    asm("mov.b64 %0, {%1, %1};" : "=l"(d) : "r"(__float_as_uint(x)));
    return d;
}
__device__ __forceinline__ float lo32(u64 v) { return __uint_as_float((unsigned)(v & 0xffffffffull)); }
__device__ __forceinline__ float hi32(u64 v) { return __uint_as_float((unsigned)(v >> 32)); }

// ---------------------------------------------------------------------------
// GEMM + bias + eval-BN + ReLU, packed f32x2 FMA inner loop.
// C[n, m] = relu( alpha[m] * (sum_k A[n,k] * W[m,k]) + beta[m] )
// Tile 128x128, BK=16, 256 threads, 8x8 per thread (accumulated as 8x4 f32x2).
// Register-prefetch pipeline: next K-tile LDG in flight during compute.
// ---------------------------------------------------------------------------
__global__ void __launch_bounds__(256, 2)
gemm_bn_relu(const float* __restrict__ A, const float* __restrict__ W,
             const float* __restrict__ bias, const float* __restrict__ gam,
             const float* __restrict__ bet, const float* __restrict__ mu,
             const float* __restrict__ var, float* __restrict__ C, int Kd)
{
    __shared__ float As[16][128];
    __shared__ float Bs[16][128];

    const int tid = threadIdx.x;
    const int tx = tid & 15;      // 0..15 -> output col groups
    const int ty = tid >> 4;      // 0..15 -> output row groups

    const float* Ab = A + (size_t)blockIdx.x * 128 * Kd;
    const float* Wb = W + (size_t)blockIdx.y * 128 * Kd;

    // loader geometry: idx in [0,512), row = idx>>2, c4 = idx&3
    const int l_row0 = (tid) >> 2,        l_c40 = (tid) & 3;
    const int l_row1 = (tid + 256) >> 2,  l_c41 = (tid + 256) & 3;

    u64 acc[8][4];
#pragma unroll
    for (int i = 0; i < 8; i++)
#pragma unroll
        for (int j = 0; j < 4; j++) acc[i][j] = 0ull;

    // prefetch first K-tile into registers
    float4 pva0 = *(const float4*)(Ab + (size_t)l_row0 * Kd + l_c40 * 4);
    float4 pva1 = *(const float4*)(Ab + (size_t)l_row1 * Kd + l_c41 * 4);
    float4 pvb0 = *(const float4*)(Wb + (size_t)l_row0 * Kd + l_c40 * 4);
    float4 pvb1 = *(const float4*)(Wb + (size_t)l_row1 * Kd + l_c41 * 4);

    for (int kt = 0; kt < Kd; kt += 16) {
        // store prefetched tile to smem
        As[l_c40 * 4 + 0][l_row0] = pva0.x;
        As[l_c40 * 4 + 1][l_row0] = pva0.y;
        As[l_c40 * 4 + 2][l_row0] = pva0.z;
        As[l_c40 * 4 + 3][l_row0] = pva0.w;
        As[l_c41 * 4 + 0][l_row1] = pva1.x;
        As[l_c41 * 4 + 1][l_row1] = pva1.y;
        As[l_c41 * 4 + 2][l_row1] = pva1.z;
        As[l_c41 * 4 + 3][l_row1] = pva1.w;
        Bs[l_c40 * 4 + 0][l_row0] = pvb0.x;
        Bs[l_c40 * 4 + 1][l_row0] = pvb0.y;
        Bs[l_c40 * 4 + 2][l_row0] = pvb0.z;
        Bs[l_c40 * 4 + 3][l_row0] = pvb0.w;
        Bs[l_c41 * 4 + 0][l_row1] = pvb1.x;
        Bs[l_c41 * 4 + 1][l_row1] = pvb1.y;
        Bs[l_c41 * 4 + 2][l_row1] = pvb1.z;
        Bs[l_c41 * 4 + 3][l_row1] = pvb1.w;
        __syncthreads();

        // issue next tile's loads (latency hidden by compute below)
        if (kt + 16 < Kd) {
            pva0 = *(const float4*)(Ab + (size_t)l_row0 * Kd + kt + 16 + l_c40 * 4);
            pva1 = *(const float4*)(Ab + (size_t)l_row1 * Kd + kt + 16 + l_c41 * 4);
            pvb0 = *(const float4*)(Wb + (size_t)l_row0 * Kd + kt + 16 + l_c40 * 4);
            pvb1 = *(const float4*)(Wb + (size_t)l_row1 * Kd + kt + 16 + l_c41 * 4);
        }

#pragma unroll
        for (int k = 0; k < 16; k++) {
            float a[8];
            float4 ta = *(const float4*)&As[k][ty * 4];
            a[0] = ta.x; a[1] = ta.y; a[2] = ta.z; a[3] = ta.w;
            float4 tb = *(const float4*)&As[k][64 + ty * 4];
            a[4] = tb.x; a[5] = tb.y; a[6] = tb.z; a[7] = tb.w;

            ulonglong2 bA = *(const ulonglong2*)&Bs[k][tx * 4];
            ulonglong2 bB = *(const ulonglong2*)&Bs[k][64 + tx * 4];
            u64 bb0 = bA.x, bb1 = bA.y, bb2 = bB.x, bb3 = bB.y;

#pragma unroll
            for (int i = 0; i < 8; i++) {
                u64 a2 = pack2(a[i]);
                acc[i][0] = fma2(a2, bb0, acc[i][0]);
                acc[i][1] = fma2(a2, bb1, acc[i][1]);
                acc[i][2] = fma2(a2, bb2, acc[i][2]);
                acc[i][3] = fma2(a2, bb3, acc[i][3]);
            }
        }
        __syncthreads();
    }

    // epilogue: per-column BN affine + relu
    float al[8], be_[8];
#pragma unroll
    for (int jh = 0; jh < 2; jh++) {
#pragma unroll
        for (int j = 0; j < 4; j++) {
            int c = blockIdx.y * 128 + jh * 64 + tx * 4 + j;
            float s = gam[c] * rsqrtf(var[c] + 1e-5f);
            al[jh * 4 + j] = s;
            be_[jh * 4 + j] = (bias[c] - mu[c]) * s + bet[c];
        }
    }

#pragma unroll
    for (int i = 0; i < 8; i++) {
        size_t row = (size_t)blockIdx.x * 128 + (i >> 2) * 64 + ty * 4 + (i & 3);
#pragma unroll
        for (int jh = 0; jh < 2; jh++) {
            float4 o;
            float c0 = lo32(acc[i][jh * 2 + 0]);
            float c1 = hi32(acc[i][jh * 2 + 0]);
            float c2 = lo32(acc[i][jh * 2 + 1]);
            float c3 = hi32(acc[i][jh * 2 + 1]);
            o.x = fmaxf(fmaf(c0, al[jh * 4 + 0], be_[jh * 4 + 0]), 0.f);
            o.y = fmaxf(fmaf(c1, al[jh * 4 + 1], be_[jh * 4 + 1]), 0.f);
            o.z = fmaxf(fmaf(c2, al[jh * 4 + 2], be_[jh * 4 + 2]), 0.f);
            o.w = fmaxf(fmaf(c3, al[jh * 4 + 3], be_[jh * 4 + 3]), 0.f);
            int col = blockIdx.y * 128 + jh * 64 + tx * 4;
            *(float4*)(C + row * COUT + col) = o;
        }
    }
}

// ---------------------------------------------------------------------------
// kNN (k=3) inverse-distance interpolation + accumulate into out.
// d2 = qq + (pp - 2 q.p); ordering needs only the parenthesized part:
// per point = 1 LDS.128 broadcast + 3 FMA.
// ---------------------------------------------------------------------------
#define PTILE 512

__global__ void __launch_bounds__(256)
interp_kernel(const float* __restrict__ p1, const float* __restrict__ p2,
              const float* __restrict__ h2, float* __restrict__ out)
{
    __shared__ float4 sp[PTILE];          // (px, py, pz, |p|^2)
    __shared__ float sq[256 * 3];
    __shared__ float sw[3][256];
    __shared__ int   si[3][256];

    const int tid = threadIdx.x;
    const int q0 = blockIdx.x * 256;
    const int scene = q0 / NPS1;

    for (int j = tid; j < 256 * 3; j += 256) sq[j] = p1[(size_t)q0 * 3 + j];
    __syncthreads();
    const float qx = sq[tid * 3 + 0];
    const float qy = sq[tid * 3 + 1];
    const float qz = sq[tid * 3 + 2];
    const float qx2 = -2.0f * qx, qy2 = -2.0f * qy, qz2 = -2.0f * qz;
    const float qq = qx * qx + qy * qy + qz * qz;

    float b0 = 3.4e38f, b1 = 3.4e38f, b2 = 3.4e38f;
    int   i0 = 0, i1 = 0, i2 = 0;

    const float* pb = p2 + (size_t)scene * NPS2 * 3;

    for (int t0 = 0; t0 < NPS2; t0 += PTILE) {
        __syncthreads();
#pragma unroll
        for (int j = tid; j < PTILE; j += 256) {
            const float* pp = pb + (size_t)(t0 + j) * 3;
            float x = pp[0], y = pp[1], z = pp[2];
            sp[j] = make_float4(x, y, z, fmaf(x, x, fmaf(y, y, z * z)));
        }
        __syncthreads();

#pragma unroll 8
        for (int j = 0; j < PTILE; j++) {
            float4 s = sp[j];
            float d = fmaf(qx2, s.x, fmaf(qy2, s.y, fmaf(qz2, s.z, s.w)));
            if (d < b2) {
                int idx = t0 + j;
                if (d < b1) {
                    b2 = b1; i2 = i1;
                    if (d < b0) { b1 = b0; i1 = i0; b0 = d; i0 = idx; }
                    else        { b1 = d;  i1 = idx; }
                } else { b2 = d; i2 = idx; }
            }
        }
    }

    // recover true squared distances, then reference's weight formula
    float d0 = qq + b0, d1 = qq + b1, d2v = qq + b2;
    float w0 = 1.0f / (sqrtf(fmaxf(d0, 1e-12f)) + 1e-8f);
    float w1 = 1.0f / (sqrtf(fmaxf(d1, 1e-12f)) + 1e-8f);
    float w2 = 1.0f / (sqrtf(fmaxf(d2v, 1e-12f)) + 1e-8f);
    float ws = w0 + w1 + w2;
    w0 /= ws; w1 /= ws; w2 /= ws;

    sw[0][tid] = w0; sw[1][tid] = w1; sw[2][tid] = w2;
    si[0][tid] = i0; si[1][tid] = i1; si[2][tid] = i2;
    __syncthreads();

    // phase 2: coalesced weighted gather, one query at a time; tid = channel
    const float* h2b = h2 + (size_t)scene * NPS2 * COUT;
#pragma unroll 2
    for (int qq_ = 0; qq_ < 256; qq_++) {
        float a0 = sw[0][qq_], a1 = sw[1][qq_], a2 = sw[2][qq_];
        const float* f0 = h2b + (size_t)si[0][qq_] * COUT;
        const float* f1 = h2b + (size_t)si[1][qq_] * COUT;
        const float* f2 = h2b + (size_t)si[2][qq_] * COUT;
        size_t o = (size_t)(q0 + qq_) * COUT + tid;
        float v = out[o];
        v = fmaf(a0, f0[tid], v);
        v = fmaf(a1, f1[tid], v);
        v = fmaf(a2, f2[tid], v);
        out[o] = v;
    }
}

// ---------------------------------------------------------------------------
extern "C" void kernel_launch(void* const* d_in, const int* in_sizes, int n_in,
                              void* d_out, int out_size)
{
    const float* p1  = (const float*)d_in[0];
    const float* x1  = (const float*)d_in[1];
    const float* p2  = (const float*)d_in[2];
    const float* x2  = (const float*)d_in[3];
    const float* W1  = (const float*)d_in[4];
    const float* b1p = (const float*)d_in[5];
    const float* g1p = (const float*)d_in[6];
    const float* be1 = (const float*)d_in[7];
    const float* m1p = (const float*)d_in[8];
    const float* v1p = (const float*)d_in[9];
    const float* W2  = (const float*)d_in[10];
    const float* b2p = (const float*)d_in[11];
    const float* g2p = (const float*)d_in[12];
    const float* be2 = (const float*)d_in[13];
    const float* m2p = (const float*)d_in[14];
    const float* v2p = (const float*)d_in[15];
    float* out = (float*)d_out;

    float* h2ptr = nullptr;
    cudaGetSymbolAddress((void**)&h2ptr, g_h2);

    // branch 1: h1 -> out
    dim3 grid1(N1_TOT / 128, COUT / 128);
    gemm_bn_relu<<<grid1, 256>>>(x1, W1, b1p, g1p, be1, m1p, v1p, out, COUT);

    // branch 2: h2 -> scratch
    dim3 grid2(N2_TOT / 128, COUT / 128);
    gemm_bn_relu<<<grid2, 256>>>(x2, W2, b2p, g2p, be2, m2p, v2p, h2ptr, CIN);

    // kNN interpolation + add
    interp_kernel<<<N1_TOT / 256, 256>>>(p1, p2, h2ptr, out);
}

// round 5
// speedup vs baseline: 1.5174x; 1.4320x over previous
#include <cuda_runtime.h>
#include <math.h>

#define N1_TOT 65536   // 4 * 16384 fine points
#define N2_TOT 16384   // 4 * 4096 coarse points
#define NPS1   16384
#define NPS2   4096
#define CIN    512
#define COUT   256

typedef unsigned long long u64;

// scratch for h2 (branch-2 features), 16 MB
__device__ float g_h2[N2_TOT * COUT];

__device__ __forceinline__ u64 fma2(u64 a, u64 b, u64 c) {
    u64 d;
    asm("fma.rn.f32x2 %0, %1, %2, %3;" : "=l"(d) : "l"(a), "l"(b), "l"(c));
    return d;
}
__device__ __forceinline__ u64 pack2(float x) {
    u64 d;
    asm("mov.b64 %0, {%1, %1};" : "=l"(d) : "r"(__float_as_uint(x)));
    return d;
}
__device__ __forceinline__ u64 packf2(float a, float b) {
    u64 d;
    asm("mov.b64 %0, {%1, %2};" : "=l"(d) : "r"(__float_as_uint(a)), "r"(__float_as_uint(b)));
    return d;
}
__device__ __forceinline__ float lo32(u64 v) { return __uint_as_float((unsigned)(v & 0xffffffffull)); }
__device__ __forceinline__ float hi32(u64 v) { return __uint_as_float((unsigned)(v >> 32)); }

// ---------------------------------------------------------------------------
// GEMM + bias + eval-BN + ReLU, packed f32x2 FMA, double-buffered smem.
// C[n, m] = relu( alpha[m] * (sum_k A[n,k] * W[m,k]) + beta[m] )
// Tile 128x128, BK=16, 256 threads, 8x8 per thread (8x4 f32x2 accum).
// ---------------------------------------------------------------------------
__global__ void __launch_bounds__(256, 2)
gemm_bn_relu(const float* __restrict__ A, const float* __restrict__ W,
             const float* __restrict__ bias, const float* __restrict__ gam,
             const float* __restrict__ bet, const float* __restrict__ mu,
             const float* __restrict__ var, float* __restrict__ C, int Kd)
{
    __shared__ float As[2][16][128];
    __shared__ float Bs[2][16][128];

    const int tid = threadIdx.x;
    const int tx = tid & 15;
    const int ty = tid >> 4;

    const float* Ab = A + (size_t)blockIdx.x * 128 * Kd;
    const float* Wb = W + (size_t)blockIdx.y * 128 * Kd;

    const int l_row0 = (tid) >> 2,        l_c40 = (tid) & 3;
    const int l_row1 = (tid + 256) >> 2,  l_c41 = (tid + 256) & 3;

    u64 acc[8][4];
#pragma unroll
    for (int i = 0; i < 8; i++)
#pragma unroll
        for (int j = 0; j < 4; j++) acc[i][j] = 0ull;

    // prefetch first K-tile
    float4 pva0 = *(const float4*)(Ab + (size_t)l_row0 * Kd + l_c40 * 4);
    float4 pva1 = *(const float4*)(Ab + (size_t)l_row1 * Kd + l_c41 * 4);
    float4 pvb0 = *(const float4*)(Wb + (size_t)l_row0 * Kd + l_c40 * 4);
    float4 pvb1 = *(const float4*)(Wb + (size_t)l_row1 * Kd + l_c41 * 4);

    // store tile 0 into buffer 0
    As[0][l_c40 * 4 + 0][l_row0] = pva0.x;
    As[0][l_c40 * 4 + 1][l_row0] = pva0.y;
    As[0][l_c40 * 4 + 2][l_row0] = pva0.z;
    As[0][l_c40 * 4 + 3][l_row0] = pva0.w;
    As[0][l_c41 * 4 + 0][l_row1] = pva1.x;
    As[0][l_c41 * 4 + 1][l_row1] = pva1.y;
    As[0][l_c41 * 4 + 2][l_row1] = pva1.z;
    As[0][l_c41 * 4 + 3][l_row1] = pva1.w;
    Bs[0][l_c40 * 4 + 0][l_row0] = pvb0.x;
    Bs[0][l_c40 * 4 + 1][l_row0] = pvb0.y;
    Bs[0][l_c40 * 4 + 2][l_row0] = pvb0.z;
    Bs[0][l_c40 * 4 + 3][l_row0] = pvb0.w;
    Bs[0][l_c41 * 4 + 0][l_row1] = pvb1.x;
    Bs[0][l_c41 * 4 + 1][l_row1] = pvb1.y;
    Bs[0][l_c41 * 4 + 2][l_row1] = pvb1.z;
    Bs[0][l_c41 * 4 + 3][l_row1] = pvb1.w;
    __syncthreads();

    const int nt = Kd >> 4;
    for (int t = 0; t < nt; t++) {
        const int cur = t & 1;
        const bool more = (t + 1 < nt);
        if (more) {
            int kt = (t + 1) << 4;
            pva0 = *(const float4*)(Ab + (size_t)l_row0 * Kd + kt + l_c40 * 4);
            pva1 = *(const float4*)(Ab + (size_t)l_row1 * Kd + kt + l_c41 * 4);
            pvb0 = *(const float4*)(Wb + (size_t)l_row0 * Kd + kt + l_c40 * 4);
            pvb1 = *(const float4*)(Wb + (size_t)l_row1 * Kd + kt + l_c41 * 4);
        }

#pragma unroll
        for (int k = 0; k < 16; k++) {
            float a[8];
            float4 ta = *(const float4*)&As[cur][k][ty * 4];
            a[0] = ta.x; a[1] = ta.y; a[2] = ta.z; a[3] = ta.w;
            float4 tb = *(const float4*)&As[cur][k][64 + ty * 4];
            a[4] = tb.x; a[5] = tb.y; a[6] = tb.z; a[7] = tb.w;

            ulonglong2 bA = *(const ulonglong2*)&Bs[cur][k][tx * 4];
            ulonglong2 bB = *(const ulonglong2*)&Bs[cur][k][64 + tx * 4];
            u64 bb0 = bA.x, bb1 = bA.y, bb2 = bB.x, bb3 = bB.y;

#pragma unroll
            for (int i = 0; i < 8; i++) {
                u64 a2 = pack2(a[i]);
                acc[i][0] = fma2(a2, bb0, acc[i][0]);
                acc[i][1] = fma2(a2, bb1, acc[i][1]);
                acc[i][2] = fma2(a2, bb2, acc[i][2]);
                acc[i][3] = fma2(a2, bb3, acc[i][3]);
            }
        }

        if (more) {
            const int nxt = cur ^ 1;
            As[nxt][l_c40 * 4 + 0][l_row0] = pva0.x;
            As[nxt][l_c40 * 4 + 1][l_row0] = pva0.y;
            As[nxt][l_c40 * 4 + 2][l_row0] = pva0.z;
            As[nxt][l_c40 * 4 + 3][l_row0] = pva0.w;
            As[nxt][l_c41 * 4 + 0][l_row1] = pva1.x;
            As[nxt][l_c41 * 4 + 1][l_row1] = pva1.y;
            As[nxt][l_c41 * 4 + 2][l_row1] = pva1.z;
            As[nxt][l_c41 * 4 + 3][l_row1] = pva1.w;
            Bs[nxt][l_c40 * 4 + 0][l_row0] = pvb0.x;
            Bs[nxt][l_c40 * 4 + 1][l_row0] = pvb0.y;
            Bs[nxt][l_c40 * 4 + 2][l_row0] = pvb0.z;
            Bs[nxt][l_c40 * 4 + 3][l_row0] = pvb0.w;
            Bs[nxt][l_c41 * 4 + 0][l_row1] = pvb1.x;
            Bs[nxt][l_c41 * 4 + 1][l_row1] = pvb1.y;
            Bs[nxt][l_c41 * 4 + 2][l_row1] = pvb1.z;
            Bs[nxt][l_c41 * 4 + 3][l_row1] = pvb1.w;
        }
        __syncthreads();
    }

    // epilogue: per-column BN affine + relu
    float al[8], be_[8];
#pragma unroll
    for (int jh = 0; jh < 2; jh++) {
#pragma unroll
        for (int j = 0; j < 4; j++) {
            int c = blockIdx.y * 128 + jh * 64 + tx * 4 + j;
            float s = gam[c] * rsqrtf(var[c] + 1e-5f);
            al[jh * 4 + j] = s;
            be_[jh * 4 + j] = (bias[c] - mu[c]) * s + bet[c];
        }
    }

#pragma unroll
    for (int i = 0; i < 8; i++) {
        size_t row = (size_t)blockIdx.x * 128 + (i >> 2) * 64 + ty * 4 + (i & 3);
#pragma unroll
        for (int jh = 0; jh < 2; jh++) {
            float4 o;
            float c0 = lo32(acc[i][jh * 2 + 0]);
            float c1 = hi32(acc[i][jh * 2 + 0]);
            float c2 = lo32(acc[i][jh * 2 + 1]);
            float c3 = hi32(acc[i][jh * 2 + 1]);
            o.x = fmaxf(fmaf(c0, al[jh * 4 + 0], be_[jh * 4 + 0]), 0.f);
            o.y = fmaxf(fmaf(c1, al[jh * 4 + 1], be_[jh * 4 + 1]), 0.f);
            o.z = fmaxf(fmaf(c2, al[jh * 4 + 2], be_[jh * 4 + 2]), 0.f);
            o.w = fmaxf(fmaf(c3, al[jh * 4 + 3], be_[jh * 4 + 3]), 0.f);
            int col = blockIdx.y * 128 + jh * 64 + tx * 4;
            *(float4*)(C + row * COUT + col) = o;
        }
    }
}

// ---------------------------------------------------------------------------
// kNN (k=3) interpolation + accumulate into out.
// Screening: quads of 4 points, packed f32x2 distance surrogate
//   d' = |p|^2 - 2 q.p   (= d^2 - |q|^2, order-equivalent)
// Track top-4 quads by quad-min (any quad with quad-min <= d3 holds a top-3
// point, so <=3 such quads exist; 4th slot absorbs fp near-tie swaps).
// Then recompute EXACT d^2 for the 16 candidate points and select/weight.
// ---------------------------------------------------------------------------
#define PTILE 512            // points per tile
#define QPT   128            // quads per tile

__global__ void __launch_bounds__(256)
interp_kernel(const float* __restrict__ p1, const float* __restrict__ p2,
              const float* __restrict__ h2, float* __restrict__ out)
{
    __shared__ ulonglong2 sX[QPT], sY[QPT], sZ[QPT], sP[QPT];  // 8 KB
    __shared__ float sq[256 * 3];
    __shared__ float sw[3][256];
    __shared__ int   si[3][256];

    const int tid = threadIdx.x;
    const int q0 = blockIdx.x * 256;
    const int scene = q0 / NPS1;

    for (int j = tid; j < 256 * 3; j += 256) sq[j] = p1[(size_t)q0 * 3 + j];
    __syncthreads();
    const float qx = sq[tid * 3 + 0];
    const float qy = sq[tid * 3 + 1];
    const float qz = sq[tid * 3 + 2];
    const u64 qxp = pack2(-2.0f * qx);
    const u64 qyp = pack2(-2.0f * qy);
    const u64 qzp = pack2(-2.0f * qz);

    // top-4 quad tracker (screened quad-min values)
    float c0 = 3.4e38f, c1 = 3.4e38f, c2 = 3.4e38f, c3 = 3.4e38f;
    int   g0 = 0, g1 = 0, g2 = 0, g3 = 0;

    const float* pb = p2 + (size_t)scene * NPS2 * 3;

    for (int t0 = 0; t0 < NPS2; t0 += PTILE) {
        __syncthreads();
        // fill tile: quad j holds points t0+4j .. t0+4j+3
        for (int j = tid; j < QPT; j += 256) {
            const float* pp = pb + (size_t)(t0 + 4 * j) * 3;   // 48B, 16B-aligned
            float4 fa = *(const float4*)(pp + 0);
            float4 fb = *(const float4*)(pp + 4);
            float4 fc = *(const float4*)(pp + 8);
            float x0 = fa.x, y0 = fa.y, z0 = fa.z;
            float x1 = fa.w, y1 = fb.x, z1 = fb.y;
            float x2 = fb.z, y2 = fb.w, z2 = fc.x;
            float x3 = fc.y, y3 = fc.z, z3 = fc.w;
            sX[j] = make_ulonglong2(packf2(x0, x1), packf2(x2, x3));
            sY[j] = make_ulonglong2(packf2(y0, y1), packf2(y2, y3));
            sZ[j] = make_ulonglong2(packf2(z0, z1), packf2(z2, z3));
            float p0 = fmaf(x0, x0, fmaf(y0, y0, z0 * z0));
            float p1_ = fmaf(x1, x1, fmaf(y1, y1, z1 * z1));
            float p2_ = fmaf(x2, x2, fmaf(y2, y2, z2 * z2));
            float p3 = fmaf(x3, x3, fmaf(y3, y3, z3 * z3));
            sP[j] = make_ulonglong2(packf2(p0, p1_), packf2(p2_, p3));
        }
        __syncthreads();

        const int qbase = t0 >> 2;
#pragma unroll 4
        for (int j = 0; j < QPT; j++) {
            ulonglong2 X = sX[j];
            ulonglong2 Y = sY[j];
            ulonglong2 Z = sZ[j];
            ulonglong2 P = sP[j];
            u64 dA = fma2(qxp, X.x, fma2(qyp, Y.x, fma2(qzp, Z.x, P.x)));
            u64 dB = fma2(qxp, X.y, fma2(qyp, Y.y, fma2(qzp, Z.y, P.y)));
            float m = fminf(fminf(lo32(dA), hi32(dA)), fminf(lo32(dB), hi32(dB)));
            if (m < c3) {
                int qi = qbase + j;
                if (m < c2) {
                    c3 = c2; g3 = g2;
                    if (m < c1) {
                        c2 = c1; g2 = g1;
                        if (m < c0) { c1 = c0; g1 = g0; c0 = m; g0 = qi; }
                        else        { c1 = m;  g1 = qi; }
                    } else { c2 = m; g2 = qi; }
                } else { c3 = m; g3 = qi; }
            }
        }
    }

    // exact re-evaluation of the 16 candidate points
    float b0 = 3.4e38f, b1 = 3.4e38f, b2v = 3.4e38f;
    int   i0 = 0, i1 = 0, i2 = 0;
    int quads[4] = {g0, g1, g2, g3};
#pragma unroll
    for (int cq = 0; cq < 4; cq++) {
        int base = quads[cq] * 4;
#pragma unroll
        for (int u = 0; u < 4; u++) {
            int pi = base + u;
            float dx = qx - pb[pi * 3 + 0];
            float dy = qy - pb[pi * 3 + 1];
            float dz = qz - pb[pi * 3 + 2];
            float d = fmaf(dx, dx, fmaf(dy, dy, dz * dz));
            if (d < b2v) {
                if (d < b1) {
                    b2v = b1; i2 = i1;
                    if (d < b0) { b1 = b0; i1 = i0; b0 = d; i0 = pi; }
                    else        { b1 = d;  i1 = pi; }
                } else { b2v = d; i2 = pi; }
            }
        }
    }

    // reference weight formula on exact distances
    float w0 = 1.0f / (sqrtf(fmaxf(b0, 1e-12f)) + 1e-8f);
    float w1 = 1.0f / (sqrtf(fmaxf(b1, 1e-12f)) + 1e-8f);
    float w2 = 1.0f / (sqrtf(fmaxf(b2v, 1e-12f)) + 1e-8f);
    float ws = w0 + w1 + w2;
    w0 /= ws; w1 /= ws; w2 /= ws;

    sw[0][tid] = w0; sw[1][tid] = w1; sw[2][tid] = w2;
    si[0][tid] = i0; si[1][tid] = i1; si[2][tid] = i2;
    __syncthreads();

    // phase 2: warp-parallel weighted gather (8 warps x 32 queries each)
    const float* h2b = h2 + (size_t)scene * NPS2 * COUT;
    const int warp = tid >> 5, lane = tid & 31;
    for (int q = warp; q < 256; q += 8) {
        float a0 = sw[0][q], a1 = sw[1][q], a2 = sw[2][q];
        const float4* f0 = (const float4*)(h2b + (size_t)si[0][q] * COUT);
        const float4* f1 = (const float4*)(h2b + (size_t)si[1][q] * COUT);
        const float4* f2 = (const float4*)(h2b + (size_t)si[2][q] * COUT);
        float4* op = (float4*)(out + (size_t)(q0 + q) * COUT);
#pragma unroll
        for (int c = 0; c < 2; c++) {
            int cc = lane + c * 32;
            float4 v  = op[cc];
            float4 t0v = f0[cc];
            float4 t1v = f1[cc];
            float4 t2v = f2[cc];
            v.x = fmaf(a2, t2v.x, fmaf(a1, t1v.x, fmaf(a0, t0v.x, v.x)));
            v.y = fmaf(a2, t2v.y, fmaf(a1, t1v.y, fmaf(a0, t0v.y, v.y)));
            v.z = fmaf(a2, t2v.z, fmaf(a1, t1v.z, fmaf(a0, t0v.z, v.z)));
            v.w = fmaf(a2, t2v.w, fmaf(a1, t1v.w, fmaf(a0, t0v.w, v.w)));
            op[cc] = v;
        }
    }
}

// ---------------------------------------------------------------------------
extern "C" void kernel_launch(void* const* d_in, const int* in_sizes, int n_in,
                              void* d_out, int out_size)
{
    const float* p1  = (const float*)d_in[0];
    const float* x1  = (const float*)d_in[1];
    const float* p2  = (const float*)d_in[2];
    const float* x2  = (const float*)d_in[3];
    const float* W1  = (const float*)d_in[4];
    const float* b1p = (const float*)d_in[5];
    const float* g1p = (const float*)d_in[6];
    const float* be1 = (const float*)d_in[7];
    const float* m1p = (const float*)d_in[8];
    const float* v1p = (const float*)d_in[9];
    const float* W2  = (const float*)d_in[10];
    const float* b2p = (const float*)d_in[11];
    const float* g2p = (const float*)d_in[12];
    const float* be2 = (const float*)d_in[13];
    const float* m2p = (const float*)d_in[14];
    const float* v2p = (const float*)d_in[15];
    float* out = (float*)d_out;

    float* h2ptr = nullptr;
    cudaGetSymbolAddress((void**)&h2ptr, g_h2);

    // branch 1: h1 -> out
    dim3 grid1(N1_TOT / 128, COUT / 128);
    gemm_bn_relu<<<grid1, 256>>>(x1, W1, b1p, g1p, be1, m1p, v1p, out, COUT);

    // branch 2: h2 -> scratch
    dim3 grid2(N2_TOT / 128, COUT / 128);
    gemm_bn_relu<<<grid2, 256>>>(x2, W2, b2p, g2p, be2, m2p, v2p, h2ptr, CIN);

    // kNN interpolation + add
    interp_kernel<<<N1_TOT / 256, 256>>>(p1, p2, h2ptr, out);
}

// round 8
// speedup vs baseline: 2.0578x; 1.3561x over previous
#include <cuda_runtime.h>
#include <cuda_bf16.h>
#include <cstdint>
#include <math.h>

#define N1_TOT 65536   // 4 * 16384 fine points
#define N2_TOT 16384   // 4 * 4096 coarse points
#define NPS1   16384
#define NPS2   4096
#define CIN    512
#define COUT   256

typedef unsigned long long u64;

// scratch for h2 (branch-2 features), 16 MB
__device__ float g_h2[N2_TOT * COUT];

// ===========================================================================
// helpers
// ===========================================================================
__device__ __forceinline__ uint32_t smem_to_u32(const void* smem_ptr) {
    uint32_t addr;
    asm("{ .reg .u64 tmp; cvta.to.shared.u64 tmp, %1; cvt.u32.u64 %0, tmp; }"
        : "=r"(addr) : "l"(smem_ptr));
    return addr;
}
__device__ __forceinline__ uint32_t bf16x2_rn(float lo, float hi) {
    uint32_t r;
    asm("cvt.rn.bf16x2.f32 %0, %1, %2;" : "=r"(r) : "f"(hi), "f"(lo));
    return r;
}
__device__ __forceinline__ float bf_lo_f(uint32_t p) { return __uint_as_float(p << 16); }
__device__ __forceinline__ float bf_hi_f(uint32_t p) { return __uint_as_float(p & 0xffff0000u); }
__device__ __forceinline__ u64 packu64(uint32_t lo, uint32_t hi) {
    return ((u64)hi << 32) | (u64)lo;
}
#define STS64(smem_addr, val) \
    asm volatile("st.shared.b64 [%0], %1;" :: "r"(smem_addr), "l"(val) : "memory")

__device__ __forceinline__ void ldm_x4(uint32_t addr, uint32_t* r) {
    asm volatile("ldmatrix.sync.aligned.m8n8.x4.shared.b16 {%0,%1,%2,%3}, [%4];"
        : "=r"(r[0]), "=r"(r[1]), "=r"(r[2]), "=r"(r[3]) : "r"(addr));
}
__device__ __forceinline__ void mma_bf16(float* c, const uint32_t* a, const uint32_t* b) {
    asm volatile(
        "mma.sync.aligned.m16n8k16.row.col.f32.bf16.bf16.f32 "
        "{%0,%1,%2,%3}, {%4,%5,%6,%7}, {%8,%9}, {%0,%1,%2,%3};"
        : "+f"(c[0]), "+f"(c[1]), "+f"(c[2]), "+f"(c[3])
        : "r"(a[0]), "r"(a[1]), "r"(a[2]), "r"(a[3]), "r"(b[0]), "r"(b[1]));
}

// ===========================================================================
// Tensor-core (mma.sync bf16) GEMM + BN + ReLU, split-precision.
//   C[m, n] = relu(alpha[n] * (sum_k A[m,k] * W[n,k]) + beta[n])
// A ~= Ahi + Alo, W ~= Whi + Wlo (bf16); acc = Ahi*Whi + Ahi*Wlo + Alo*Whi.
// Tile 128(M) x 128(N), BK=32. 8 warps (2x4), warp tile 64x32.
// smem pitch 80 B (32 bf16 + 8 pad) -> ldmatrix mostly conflict-free.
// ===========================================================================
#define SPITCH 80

__global__ void __launch_bounds__(256)
gemm_mma(const float* __restrict__ A, const float* __restrict__ W,
         const float* __restrict__ bias, const float* __restrict__ gam,
         const float* __restrict__ bet, const float* __restrict__ mu,
         const float* __restrict__ var, float* __restrict__ C, int Kd)
{
    __shared__ __align__(16) uint8_t sAhi[128 * SPITCH];
    __shared__ __align__(16) uint8_t sAlo[128 * SPITCH];
    __shared__ __align__(16) uint8_t sWhi[128 * SPITCH];
    __shared__ __align__(16) uint8_t sWlo[128 * SPITCH];
    __shared__ float s_al[128];
    __shared__ float s_be[128];

    const int tid  = threadIdx.x;
    const int wid  = tid >> 5;
    const int lane = tid & 31;
    const int bm   = blockIdx.x;
    const int by   = blockIdx.y;

    if (tid < 128) {
        int c = by * 128 + tid;
        float s = gam[c] * rsqrtf(var[c] + 1e-5f);
        s_al[tid] = s;
        s_be[tid] = (bias[c] - mu[c]) * s + bet[c];
    }

    const uint32_t uAhi = smem_to_u32(sAhi);
    const uint32_t uAlo = smem_to_u32(sAlo);
    const uint32_t uWhi = smem_to_u32(sWhi);
    const uint32_t uWlo = smem_to_u32(sWlo);

    // loader mapping: thread -> row tid/2 (0..127), col half (tid&1)*16
    const int lrow = tid >> 1;
    const int lcol = (tid & 1) * 16;
    const float* srcA0 = A + ((size_t)(bm * 128 + lrow)) * Kd + lcol;
    const float* srcW0 = W + ((size_t)(by * 128 + lrow)) * Kd + lcol;
    const uint32_t stA = lrow * SPITCH + lcol * 2;

    // warp tiling
    const int warp_m = wid >> 2;   // 0-1
    const int warp_n = wid & 3;    // 0-3
    // ldmatrix lane address components
    const int a_row = (lane & 15);
    const int a_ko  = (lane >> 4) * 8;
    const int b_n   = ((lane >> 4) & 1) * 8 + (lane & 7);
    const int b_ko  = ((lane >> 3) & 1) * 8;

    float acc[4][4][4];
#pragma unroll
    for (int mt = 0; mt < 4; mt++)
#pragma unroll
        for (int j = 0; j < 4; j++)
#pragma unroll
            for (int e = 0; e < 4; e++) acc[mt][j][e] = 0.0f;

    for (int kt = 0; kt < Kd; kt += 32) {
        __syncthreads();
        // ---- load + hi/lo convert A and W chunks (128x32 fp32 each) ----
        {
            const float* sa = srcA0 + kt;
            const float* sw_ = srcW0 + kt;
#pragma unroll
            for (int j = 0; j < 4; j++) {
                float4 v = *(const float4*)(sa + 4 * j);
                uint32_t h0 = bf16x2_rn(v.x, v.y);
                uint32_t h1 = bf16x2_rn(v.z, v.w);
                uint32_t l0 = bf16x2_rn(v.x - bf_lo_f(h0), v.y - bf_hi_f(h0));
                uint32_t l1 = bf16x2_rn(v.z - bf_lo_f(h1), v.w - bf_hi_f(h1));
                uint32_t ad = stA + 8 * j;
                STS64(uAhi + ad, packu64(h0, h1));
                STS64(uAlo + ad, packu64(l0, l1));

                float4 u = *(const float4*)(sw_ + 4 * j);
                uint32_t H0 = bf16x2_rn(u.x, u.y);
                uint32_t H1 = bf16x2_rn(u.z, u.w);
                uint32_t L0 = bf16x2_rn(u.x - bf_lo_f(H0), u.y - bf_hi_f(H0));
                uint32_t L1 = bf16x2_rn(u.z - bf_lo_f(H1), u.w - bf_hi_f(H1));
                STS64(uWhi + ad, packu64(H0, H1));
                STS64(uWlo + ad, packu64(L0, L1));
            }
        }
        __syncthreads();

        // ---- compute: 2 k16 steps ----
#pragma unroll
        for (int ks = 0; ks < 2; ks++) {
            const uint32_t a_off = (uint32_t)((warp_m * 64 + a_row) * SPITCH + (ks * 16 + a_ko) * 2);
            const uint32_t b_off = (uint32_t)((warp_n * 32 + b_n) * SPITCH + (ks * 16 + b_ko) * 2);

            uint32_t ah[4][4], bh[2][4], bl[2][4];
#pragma unroll
            for (int mt = 0; mt < 4; mt++)
                ldm_x4(uAhi + a_off + mt * 16 * SPITCH, ah[mt]);
#pragma unroll
            for (int ng = 0; ng < 2; ng++) {
                ldm_x4(uWhi + b_off + ng * 16 * SPITCH, bh[ng]);
                ldm_x4(uWlo + b_off + ng * 16 * SPITCH, bl[ng]);
            }

            // Ahi*Whi + Ahi*Wlo
#pragma unroll
            for (int mt = 0; mt < 4; mt++)
#pragma unroll
                for (int j = 0; j < 4; j++) {
                    mma_bf16(acc[mt][j], ah[mt], &bh[j >> 1][(j & 1) * 2]);
                    mma_bf16(acc[mt][j], ah[mt], &bl[j >> 1][(j & 1) * 2]);
                }

            // Alo*Whi (reuse A fragment registers)
#pragma unroll
            for (int mt = 0; mt < 4; mt++)
                ldm_x4(uAlo + a_off + mt * 16 * SPITCH, ah[mt]);
#pragma unroll
            for (int mt = 0; mt < 4; mt++)
#pragma unroll
                for (int j = 0; j < 4; j++)
                    mma_bf16(acc[mt][j], ah[mt], &bh[j >> 1][(j & 1) * 2]);
        }
    }

    // ---- epilogue: BN + ReLU, direct global stores ----
#pragma unroll
    for (int mt = 0; mt < 4; mt++) {
        int r0 = bm * 128 + warp_m * 64 + mt * 16 + (lane >> 2);
#pragma unroll
        for (int j = 0; j < 4; j++) {
            int lc = warp_n * 32 + j * 8 + (lane & 3) * 2;
            int gc = by * 128 + lc;
            float a0 = s_al[lc], a1 = s_al[lc + 1];
            float e0 = s_be[lc], e1 = s_be[lc + 1];
            float2 o;
            o.x = fmaxf(fmaf(acc[mt][j][0], a0, e0), 0.f);
            o.y = fmaxf(fmaf(acc[mt][j][1], a1, e1), 0.f);
            *(float2*)(C + (size_t)r0 * 256 + gc) = o;
            o.x = fmaxf(fmaf(acc[mt][j][2], a0, e0), 0.f);
            o.y = fmaxf(fmaf(acc[mt][j][3], a1, e1), 0.f);
            *(float2*)(C + (size_t)(r0 + 8) * 256 + gc) = o;
        }
    }
}

// ===========================================================================
// interp helpers (packed f32x2)
// ===========================================================================
__device__ __forceinline__ u64 fma2(u64 a, u64 b, u64 c) {
    u64 d;
    asm("fma.rn.f32x2 %0, %1, %2, %3;" : "=l"(d) : "l"(a), "l"(b), "l"(c));
    return d;
}
__device__ __forceinline__ u64 pack2(float x) {
    u64 d;
    asm("mov.b64 %0, {%1, %1};" : "=l"(d) : "r"(__float_as_uint(x)));
    return d;
}
__device__ __forceinline__ u64 packf2(float a, float b) {
    u64 d;
    asm("mov.b64 %0, {%1, %2};" : "=l"(d) : "r"(__float_as_uint(a)), "r"(__float_as_uint(b)));
    return d;
}
__device__ __forceinline__ float lo32(u64 v) { return __uint_as_float((unsigned)(v & 0xffffffffull)); }
__device__ __forceinline__ float hi32(u64 v) { return __uint_as_float((unsigned)(v >> 32)); }

// ---------------------------------------------------------------------------
// kNN (k=3) interpolation + accumulate into out.
// Quad screening with top-4 quad tracker, then exact re-evaluation of the 16
// candidate points (provably exact selection; see round-4 notes).
// ---------------------------------------------------------------------------
#define PTILE 512            // points per tile
#define QPT   128            // quads per tile

__global__ void __launch_bounds__(256)
interp_kernel(const float* __restrict__ p1, const float* __restrict__ p2,
              const float* __restrict__ h2, float* __restrict__ out)
{
    __shared__ ulonglong2 sX[QPT], sY[QPT], sZ[QPT], sP[QPT];  // 8 KB
    __shared__ float sq[256 * 3];
    __shared__ float sw[3][256];
    __shared__ int   si[3][256];

    const int tid = threadIdx.x;
    const int q0 = blockIdx.x * 256;
    const int scene = q0 / NPS1;

    for (int j = tid; j < 256 * 3; j += 256) sq[j] = p1[(size_t)q0 * 3 + j];
    __syncthreads();
    const float qx = sq[tid * 3 + 0];
    const float qy = sq[tid * 3 + 1];
    const float qz = sq[tid * 3 + 2];
    const u64 qxp = pack2(-2.0f * qx);
    const u64 qyp = pack2(-2.0f * qy);
    const u64 qzp = pack2(-2.0f * qz);

    float c0 = 3.4e38f, c1 = 3.4e38f, c2 = 3.4e38f, c3 = 3.4e38f;
    int   g0 = 0, g1 = 0, g2 = 0, g3 = 0;

    const float* pb = p2 + (size_t)scene * NPS2 * 3;

    for (int t0 = 0; t0 < NPS2; t0 += PTILE) {
        __syncthreads();
        for (int j = tid; j < QPT; j += 256) {
            const float* pp = pb + (size_t)(t0 + 4 * j) * 3;
            float4 fa = *(const float4*)(pp + 0);
            float4 fb = *(const float4*)(pp + 4);
            float4 fc = *(const float4*)(pp + 8);
            float x0 = fa.x, y0 = fa.y, z0 = fa.z;
            float x1 = fa.w, y1 = fb.x, z1 = fb.y;
            float x2 = fb.z, y2 = fb.w, z2 = fc.x;
            float x3 = fc.y, y3 = fc.z, z3 = fc.w;
            sX[j] = make_ulonglong2(packf2(x0, x1), packf2(x2, x3));
            sY[j] = make_ulonglong2(packf2(y0, y1), packf2(y2, y3));
            sZ[j] = make_ulonglong2(packf2(z0, z1), packf2(z2, z3));
            float p0 = fmaf(x0, x0, fmaf(y0, y0, z0 * z0));
            float p1_ = fmaf(x1, x1, fmaf(y1, y1, z1 * z1));
            float p2_ = fmaf(x2, x2, fmaf(y2, y2, z2 * z2));
            float p3 = fmaf(x3, x3, fmaf(y3, y3, z3 * z3));
            sP[j] = make_ulonglong2(packf2(p0, p1_), packf2(p2_, p3));
        }
        __syncthreads();

        const int qbase = t0 >> 2;
#pragma unroll 4
        for (int j = 0; j < QPT; j++) {
            ulonglong2 X = sX[j];
            ulonglong2 Y = sY[j];
            ulonglong2 Z = sZ[j];
            ulonglong2 P = sP[j];
            u64 dA = fma2(qxp, X.x, fma2(qyp, Y.x, fma2(qzp, Z.x, P.x)));
            u64 dB = fma2(qxp, X.y, fma2(qyp, Y.y, fma2(qzp, Z.y, P.y)));
            float m = fminf(fminf(lo32(dA), hi32(dA)), fminf(lo32(dB), hi32(dB)));
            if (m < c3) {
                int qi = qbase + j;
                if (m < c2) {
                    c3 = c2; g3 = g2;
                    if (m < c1) {
                        c2 = c1; g2 = g1;
                        if (m < c0) { c1 = c0; g1 = g0; c0 = m; g0 = qi; }
                        else        { c1 = m;  g1 = qi; }
                    } else { c2 = m; g2 = qi; }
                } else { c3 = m; g3 = qi; }
            }
        }
    }

    // exact re-evaluation of the 16 candidate points
    float b0 = 3.4e38f, b1 = 3.4e38f, b2v = 3.4e38f;
    int   i0 = 0, i1 = 0, i2 = 0;
    int quads[4] = {g0, g1, g2, g3};
#pragma unroll
    for (int cq = 0; cq < 4; cq++) {
        int base = quads[cq] * 4;
#pragma unroll
        for (int u = 0; u < 4; u++) {
            int pi = base + u;
            float dx = qx - pb[pi * 3 + 0];
            float dy = qy - pb[pi * 3 + 1];
            float dz = qz - pb[pi * 3 + 2];
            float d = fmaf(dx, dx, fmaf(dy, dy, dz * dz));
            if (d < b2v) {
                if (d < b1) {
                    b2v = b1; i2 = i1;
                    if (d < b0) { b1 = b0; i1 = i0; b0 = d; i0 = pi; }
                    else        { b1 = d;  i1 = pi; }
                } else { b2v = d; i2 = pi; }
            }
        }
    }

    float w0 = 1.0f / (sqrtf(fmaxf(b0, 1e-12f)) + 1e-8f);
    float w1 = 1.0f / (sqrtf(fmaxf(b1, 1e-12f)) + 1e-8f);
    float w2 = 1.0f / (sqrtf(fmaxf(b2v, 1e-12f)) + 1e-8f);
    float ws = w0 + w1 + w2;
    w0 /= ws; w1 /= ws; w2 /= ws;

    sw[0][tid] = w0; sw[1][tid] = w1; sw[2][tid] = w2;
    si[0][tid] = i0; si[1][tid] = i1; si[2][tid] = i2;
    __syncthreads();

    // phase 2: warp-parallel weighted gather (8 warps x queries)
    const float* h2b = h2 + (size_t)scene * NPS2 * COUT;
    const int warp = tid >> 5, lane = tid & 31;
    for (int q = warp; q < 256; q += 8) {
        float a0 = sw[0][q], a1 = sw[1][q], a2 = sw[2][q];
        const float4* f0 = (const float4*)(h2b + (size_t)si[0][q] * COUT);
        const float4* f1 = (const float4*)(h2b + (size_t)si[1][q] * COUT);
        const float4* f2 = (const float4*)(h2b + (size_t)si[2][q] * COUT);
        float4* op = (float4*)(out + (size_t)(q0 + q) * COUT);
#pragma unroll
        for (int c = 0; c < 2; c++) {
            int cc = lane + c * 32;
            float4 v  = op[cc];
            float4 t0v = f0[cc];
            float4 t1v = f1[cc];
            float4 t2v = f2[cc];
            v.x = fmaf(a2, t2v.x, fmaf(a1, t1v.x, fmaf(a0, t0v.x, v.x)));
            v.y = fmaf(a2, t2v.y, fmaf(a1, t1v.y, fmaf(a0, t0v.y, v.y)));
            v.z = fmaf(a2, t2v.z, fmaf(a1, t1v.z, fmaf(a0, t0v.z, v.z)));
            v.w = fmaf(a2, t2v.w, fmaf(a1, t1v.w, fmaf(a0, t0v.w, v.w)));
            op[cc] = v;
        }
    }
}

// ---------------------------------------------------------------------------
extern "C" void kernel_launch(void* const* d_in, const int* in_sizes, int n_in,
                              void* d_out, int out_size)
{
    const float* p1  = (const float*)d_in[0];
    const float* x1  = (const float*)d_in[1];
    const float* p2  = (const float*)d_in[2];
    const float* x2  = (const float*)d_in[3];
    const float* W1  = (const float*)d_in[4];
    const float* b1p = (const float*)d_in[5];
    const float* g1p = (const float*)d_in[6];
    const float* be1 = (const float*)d_in[7];
    const float* m1p = (const float*)d_in[8];
    const float* v1p = (const float*)d_in[9];
    const float* W2  = (const float*)d_in[10];
    const float* b2p = (const float*)d_in[11];
    const float* g2p = (const float*)d_in[12];
    const float* be2 = (const float*)d_in[13];
    const float* m2p = (const float*)d_in[14];
    const float* v2p = (const float*)d_in[15];
    float* out = (float*)d_out;

    float* h2ptr = nullptr;
    cudaGetSymbolAddress((void**)&h2ptr, g_h2);

    // branch 1: h1 -> out  (M=65536, K=256)
    gemm_mma<<<dim3(N1_TOT / 128, 2), 256>>>(x1, W1, b1p, g1p, be1, m1p, v1p, out, COUT);

    // branch 2: h2 -> scratch  (M=16384, K=512)
    gemm_mma<<<dim3(N2_TOT / 128, 2), 256>>>(x2, W2, b2p, g2p, be2, m2p, v2p, h2ptr, CIN);

    // kNN interpolation + add
    interp_kernel<<<N1_TOT / 256, 256>>>(p1, p2, h2ptr, out);
}